// round 1
// baseline (speedup 1.0000x reference)
#include <cuda_runtime.h>

#define S_LEN   2048
#define DMODEL  1024
#define NHEAD   16
#define HDIM    64
#define BATCH   2
#define M_ROWS  (BATCH * S_LEN)   /* 4096 */

// Scratch (allocation-free rule: __device__ globals). 16 MB each.
__device__ float g_Q[BATCH * NHEAD * S_LEN * HDIM];
__device__ float g_K[BATCH * NHEAD * S_LEN * HDIM];
__device__ float g_V[BATCH * NHEAD * S_LEN * HDIM];
__device__ float g_attn[BATCH * S_LEN * DMODEL];

// ---------------------------------------------------------------------------
// GEMM + bias:  C[m,n] = sum_k A[m,k] * W[n,k] + bias[n]
// A: [4096,1024] row-major, W: [1024,1024] row-major (torch Linear weight).
// headsplit=1: write C to [B,H,S,64] layout; else flat [m,1024].
// 64x64 tile, BK=16, 256 threads, 4x4 register blocking.
// ---------------------------------------------------------------------------
__global__ __launch_bounds__(256) void gemm_bias_kernel(
    const float* __restrict__ A, const float* __restrict__ W,
    const float* __restrict__ bias, float* __restrict__ C, int headsplit)
{
    __shared__ float As[16][64];
    __shared__ float Bs[16][64];

    const int tid = threadIdx.x;
    const int tx = tid & 15;        // 0..15 -> n sub-tile
    const int ty = tid >> 4;        // 0..15 -> m sub-tile
    const int bm = blockIdx.x;      // 0..63
    const int bn = blockIdx.y;      // 0..15
    const int loadRow = tid >> 2;   // 0..63
    const int loadK   = (tid & 3) << 2;

    const float* Ap = A + (size_t)(bm * 64 + loadRow) * DMODEL + loadK;
    const float* Wp = W + (size_t)(bn * 64 + loadRow) * DMODEL + loadK;

    float acc[4][4] = {};

    for (int k0 = 0; k0 < DMODEL; k0 += 16) {
        float4 av = *(const float4*)(Ap + k0);
        float4 wv = *(const float4*)(Wp + k0);
        __syncthreads();
        As[loadK + 0][loadRow] = av.x; As[loadK + 1][loadRow] = av.y;
        As[loadK + 2][loadRow] = av.z; As[loadK + 3][loadRow] = av.w;
        Bs[loadK + 0][loadRow] = wv.x; Bs[loadK + 1][loadRow] = wv.y;
        Bs[loadK + 2][loadRow] = wv.z; Bs[loadK + 3][loadRow] = wv.w;
        __syncthreads();
#pragma unroll
        for (int kk = 0; kk < 16; kk++) {
            float4 a4 = *(const float4*)&As[kk][ty << 2];
            float4 b4 = *(const float4*)&Bs[kk][tx << 2];
            float aa[4] = {a4.x, a4.y, a4.z, a4.w};
            float bb[4] = {b4.x, b4.y, b4.z, b4.w};
#pragma unroll
            for (int i = 0; i < 4; i++)
#pragma unroll
                for (int j = 0; j < 4; j++)
                    acc[i][j] += aa[i] * bb[j];
        }
    }

#pragma unroll
    for (int i = 0; i < 4; i++) {
        const int m = bm * 64 + (ty << 2) + i;
#pragma unroll
        for (int j = 0; j < 4; j++) {
            const int n = bn * 64 + (tx << 2) + j;
            float v = acc[i][j] + bias[n];
            if (headsplit) {
                const int b = m >> 11, s = m & (S_LEN - 1);
                const int h = n >> 6,  d = n & 63;
                C[((size_t)((b * NHEAD + h) * S_LEN + s)) * HDIM + d] = v;
            } else {
                C[(size_t)m * DMODEL + n] = v;
            }
        }
    }
}

// ---------------------------------------------------------------------------
// Flash attention, fp32, full (non-causal) softmax.
// grid = (S/64 q-tiles, B*H). 128 threads: r = tid&63 (query row within tile),
// half = tid>>6 (key-half for scores / d-half for O accumulation).
// K and V time-share one smem tile. Scores stored transposed Ps[key][row]
// so every smem access is either a broadcast or lane-consecutive.
// ---------------------------------------------------------------------------
__global__ __launch_bounds__(128) void attn_kernel(
    const float* __restrict__ Q, const float* __restrict__ K,
    const float* __restrict__ V, float* __restrict__ Out)
{
    __shared__ float KVs[64][64];   // K tile, then V tile
    __shared__ float Ps[64][64];    // [key][row]
    __shared__ float mred[2][64];
    __shared__ float lred[2][64];

    const int tid  = threadIdx.x;
    const int r    = tid & 63;
    const int half = tid >> 6;
    const int qtile = blockIdx.x;
    const int bh    = blockIdx.y;

    // Q row -> registers
    const float* Qbase = Q + ((size_t)bh * S_LEN + qtile * 64 + r) * HDIM;
    float4 q[16];
#pragma unroll
    for (int i = 0; i < 16; i++) q[i] = *(const float4*)(Qbase + i * 4);

    float4 o[8];
#pragma unroll
    for (int i = 0; i < 8; i++) o[i] = make_float4(0.f, 0.f, 0.f, 0.f);
    float m = -1e30f, l = 0.f;

    const float* Kbh = K + (size_t)bh * S_LEN * HDIM;
    const float* Vbh = V + (size_t)bh * S_LEN * HDIM;

    for (int kt = 0; kt < S_LEN / 64; kt++) {
        // --- load K tile (1024 float4, 8 per thread) ---
        {
            const float4* src = (const float4*)(Kbh + (size_t)kt * 64 * HDIM);
            float4* dst = (float4*)&KVs[0][0];
#pragma unroll
            for (int i = 0; i < 8; i++) dst[tid + i * 128] = src[tid + i * 128];
        }
        __syncthreads();

        // --- scores for this half's 32 keys (raw, scaled) ---
        float tmax = -1e30f;
#pragma unroll 2
        for (int jj = 0; jj < 32; jj++) {
            const int j = (half << 5) + jj;
            float acc = 0.f;
#pragma unroll
            for (int dd = 0; dd < 16; dd++) {
                float4 kv = *(const float4*)&KVs[j][dd << 2];
                acc += q[dd].x * kv.x + q[dd].y * kv.y +
                       q[dd].z * kv.z + q[dd].w * kv.w;
            }
            acc *= 0.125f;            // 1/sqrt(64)
            Ps[j][r] = acc;
            tmax = fmaxf(tmax, acc);
        }
        mred[half][r] = tmax;
        __syncthreads();

        const float mnew = fmaxf(m, fmaxf(mred[0][r], mred[1][r]));
        float lpart = 0.f;
#pragma unroll 4
        for (int jj = 0; jj < 32; jj++) {
            const int j = (half << 5) + jj;
            float p = __expf(Ps[j][r] - mnew);
            Ps[j][r] = p;
            lpart += p;
        }
        lred[half][r] = lpart;
        const float alpha = __expf(m - mnew);
        m = mnew;
#pragma unroll
        for (int i = 0; i < 8; i++) {
            o[i].x *= alpha; o[i].y *= alpha; o[i].z *= alpha; o[i].w *= alpha;
        }
        __syncthreads();              // Ps(p)/lred visible; K reads done
        l = l * alpha + lred[0][r] + lred[1][r];

        // --- load V tile into same buffer ---
        {
            const float4* src = (const float4*)(Vbh + (size_t)kt * 64 * HDIM);
            float4* dst = (float4*)&KVs[0][0];
#pragma unroll
            for (int i = 0; i < 8; i++) dst[tid + i * 128] = src[tid + i * 128];
        }
        __syncthreads();

        // --- O[r, half*32 .. +31] += sum_j P[j,r] * V[j, dslice] ---
#pragma unroll 2
        for (int j = 0; j < 64; j++) {
            const float p = Ps[j][r];
            const float4* vrow = (const float4*)&KVs[j][half << 5];
#pragma unroll
            for (int i = 0; i < 8; i++) {
                float4 v4 = vrow[i];
                o[i].x += p * v4.x; o[i].y += p * v4.y;
                o[i].z += p * v4.z; o[i].w += p * v4.w;
            }
        }
        __syncthreads();              // before next tile overwrites KVs/Ps
    }

    const float inv = 1.f / l;
    const int b = bh >> 4, h = bh & 15;
    float* dst = Out + ((size_t)(b * S_LEN + qtile * 64 + r)) * DMODEL
                     + h * HDIM + (half << 5);
#pragma unroll
    for (int i = 0; i < 8; i++) {
        float4 v4 = o[i];
        v4.x *= inv; v4.y *= inv; v4.z *= inv; v4.w *= inv;
        ((float4*)dst)[i] = v4;
    }
}

// ---------------------------------------------------------------------------
extern "C" void kernel_launch(void* const* d_in, const int* in_sizes, int n_in,
                              void* d_out, int out_size)
{
    const float* query = (const float*)d_in[0];
    const float* key   = (const float*)d_in[1];
    const float* value = (const float*)d_in[2];
    const float* Wq = (const float*)d_in[3];
    const float* bq = (const float*)d_in[4];
    const float* Wk = (const float*)d_in[5];
    const float* bk = (const float*)d_in[6];
    const float* Wv = (const float*)d_in[7];
    const float* bv = (const float*)d_in[8];
    const float* Wo = (const float*)d_in[9];
    const float* bo = (const float*)d_in[10];
    float* out = (float*)d_out;

    float *pQ, *pK, *pV, *pA;
    cudaGetSymbolAddress((void**)&pQ, g_Q);
    cudaGetSymbolAddress((void**)&pK, g_K);
    cudaGetSymbolAddress((void**)&pV, g_V);
    cudaGetSymbolAddress((void**)&pA, g_attn);

    dim3 ggrid(M_ROWS / 64, DMODEL / 64);
    gemm_bias_kernel<<<ggrid, 256>>>(query, Wq, bq, pQ, 1);
    gemm_bias_kernel<<<ggrid, 256>>>(key,   Wk, bk, pK, 1);
    gemm_bias_kernel<<<ggrid, 256>>>(value, Wv, bv, pV, 1);

    dim3 agrid(S_LEN / 64, BATCH * NHEAD);
    attn_kernel<<<agrid, 128>>>(pQ, pK, pV, pA);

    gemm_bias_kernel<<<ggrid, 256>>>(pA, Wo, bo, out, 0);
}

// round 2
// speedup vs baseline: 1.0016x; 1.0016x over previous
#include <cuda_runtime.h>

#define S_LEN   2048
#define DMODEL  1024
#define NHEAD   16
#define HDIM    64
#define BATCH   2
#define M_ROWS  (BATCH * S_LEN)   /* 4096 */

// Scratch (allocation-free rule: __device__ globals). 16 MB each.
__device__ float g_Q[BATCH * NHEAD * S_LEN * HDIM];
__device__ float g_K[BATCH * NHEAD * S_LEN * HDIM];
__device__ float g_V[BATCH * NHEAD * S_LEN * HDIM];
__device__ float g_attn[BATCH * S_LEN * DMODEL];

// ---------------------------------------------------------------------------
// GEMM + bias:  C[m,n] = sum_k A[m,k] * W[n,k] + bias[n]
// A: [4096,1024] row-major, W: [1024,1024] row-major (torch Linear weight).
// headsplit=1: write C to [B,H,S,64] layout; else flat [m,1024].
// 64x64 tile, BK=16, 256 threads, 4x4 register blocking.
// ---------------------------------------------------------------------------
__global__ __launch_bounds__(256) void gemm_bias_kernel(
    const float* __restrict__ A, const float* __restrict__ W,
    const float* __restrict__ bias, float* __restrict__ C, int headsplit)
{
    __shared__ float As[16][64];
    __shared__ float Bs[16][64];

    const int tid = threadIdx.x;
    const int tx = tid & 15;        // 0..15 -> n sub-tile
    const int ty = tid >> 4;        // 0..15 -> m sub-tile
    const int bm = blockIdx.x;      // 0..63
    const int bn = blockIdx.y;      // 0..15
    const int loadRow = tid >> 2;   // 0..63
    const int loadK   = (tid & 3) << 2;

    const float* Ap = A + (size_t)(bm * 64 + loadRow) * DMODEL + loadK;
    const float* Wp = W + (size_t)(bn * 64 + loadRow) * DMODEL + loadK;

    float acc[4][4] = {};

    for (int k0 = 0; k0 < DMODEL; k0 += 16) {
        float4 av = *(const float4*)(Ap + k0);
        float4 wv = *(const float4*)(Wp + k0);
        __syncthreads();
        As[loadK + 0][loadRow] = av.x; As[loadK + 1][loadRow] = av.y;
        As[loadK + 2][loadRow] = av.z; As[loadK + 3][loadRow] = av.w;
        Bs[loadK + 0][loadRow] = wv.x; Bs[loadK + 1][loadRow] = wv.y;
        Bs[loadK + 2][loadRow] = wv.z; Bs[loadK + 3][loadRow] = wv.w;
        __syncthreads();
#pragma unroll
        for (int kk = 0; kk < 16; kk++) {
            float4 a4 = *(const float4*)&As[kk][ty << 2];
            float4 b4 = *(const float4*)&Bs[kk][tx << 2];
            float aa[4] = {a4.x, a4.y, a4.z, a4.w};
            float bb[4] = {b4.x, b4.y, b4.z, b4.w};
#pragma unroll
            for (int i = 0; i < 4; i++)
#pragma unroll
                for (int j = 0; j < 4; j++)
                    acc[i][j] += aa[i] * bb[j];
        }
    }

#pragma unroll
    for (int i = 0; i < 4; i++) {
        const int m = bm * 64 + (ty << 2) + i;
#pragma unroll
        for (int j = 0; j < 4; j++) {
            const int n = bn * 64 + (tx << 2) + j;
            float v = acc[i][j] + bias[n];
            if (headsplit) {
                const int b = m >> 11, s = m & (S_LEN - 1);
                const int h = n >> 6,  d = n & 63;
                C[((size_t)((b * NHEAD + h) * S_LEN + s)) * HDIM + d] = v;
            } else {
                C[(size_t)m * DMODEL + n] = v;
            }
        }
    }
}

// ---------------------------------------------------------------------------
// Flash attention, fp32, full (non-causal) softmax.
// grid = (S/64 q-tiles, B*H). 128 threads: r = tid&63 (query row within tile),
// half = tid>>6 (key-half for scores / d-half for O accumulation).
// K and V time-share one smem tile. Scores stored transposed Ps[key][row]
// so every smem access is either a broadcast or lane-consecutive.
// ---------------------------------------------------------------------------
__global__ __launch_bounds__(128) void attn_kernel(
    const float* __restrict__ Q, const float* __restrict__ K,
    const float* __restrict__ V, float* __restrict__ Out)
{
    __shared__ float KVs[64][64];   // K tile, then V tile
    __shared__ float Ps[64][64];    // [key][row]
    __shared__ float mred[2][64];
    __shared__ float lred[2][64];

    const int tid  = threadIdx.x;
    const int r    = tid & 63;
    const int half = tid >> 6;
    const int qtile = blockIdx.x;
    const int bh    = blockIdx.y;

    // Q row -> registers
    const float* Qbase = Q + ((size_t)bh * S_LEN + qtile * 64 + r) * HDIM;
    float4 q[16];
#pragma unroll
    for (int i = 0; i < 16; i++) q[i] = *(const float4*)(Qbase + i * 4);

    float4 o[8];
#pragma unroll
    for (int i = 0; i < 8; i++) o[i] = make_float4(0.f, 0.f, 0.f, 0.f);
    float m = -1e30f, l = 0.f;

    const float* Kbh = K + (size_t)bh * S_LEN * HDIM;
    const float* Vbh = V + (size_t)bh * S_LEN * HDIM;

    for (int kt = 0; kt < S_LEN / 64; kt++) {
        // --- load K tile (1024 float4, 8 per thread) ---
        {
            const float4* src = (const float4*)(Kbh + (size_t)kt * 64 * HDIM);
            float4* dst = (float4*)&KVs[0][0];
#pragma unroll
            for (int i = 0; i < 8; i++) dst[tid + i * 128] = src[tid + i * 128];
        }
        __syncthreads();

        // --- scores for this half's 32 keys (raw, scaled) ---
        float tmax = -1e30f;
#pragma unroll 2
        for (int jj = 0; jj < 32; jj++) {
            const int j = (half << 5) + jj;
            float acc = 0.f;
#pragma unroll
            for (int dd = 0; dd < 16; dd++) {
                float4 kv = *(const float4*)&KVs[j][dd << 2];
                acc += q[dd].x * kv.x + q[dd].y * kv.y +
                       q[dd].z * kv.z + q[dd].w * kv.w;
            }
            acc *= 0.125f;            // 1/sqrt(64)
            Ps[j][r] = acc;
            tmax = fmaxf(tmax, acc);
        }
        mred[half][r] = tmax;
        __syncthreads();

        const float mnew = fmaxf(m, fmaxf(mred[0][r], mred[1][r]));
        float lpart = 0.f;
#pragma unroll 4
        for (int jj = 0; jj < 32; jj++) {
            const int j = (half << 5) + jj;
            float p = __expf(Ps[j][r] - mnew);
            Ps[j][r] = p;
            lpart += p;
        }
        lred[half][r] = lpart;
        const float alpha = __expf(m - mnew);
        m = mnew;
#pragma unroll
        for (int i = 0; i < 8; i++) {
            o[i].x *= alpha; o[i].y *= alpha; o[i].z *= alpha; o[i].w *= alpha;
        }
        __syncthreads();              // Ps(p)/lred visible; K reads done
        l = l * alpha + lred[0][r] + lred[1][r];

        // --- load V tile into same buffer ---
        {
            const float4* src = (const float4*)(Vbh + (size_t)kt * 64 * HDIM);
            float4* dst = (float4*)&KVs[0][0];
#pragma unroll
            for (int i = 0; i < 8; i++) dst[tid + i * 128] = src[tid + i * 128];
        }
        __syncthreads();

        // --- O[r, half*32 .. +31] += sum_j P[j,r] * V[j, dslice] ---
#pragma unroll 2
        for (int j = 0; j < 64; j++) {
            const float p = Ps[j][r];
            const float4* vrow = (const float4*)&KVs[j][half << 5];
#pragma unroll
            for (int i = 0; i < 8; i++) {
                float4 v4 = vrow[i];
                o[i].x += p * v4.x; o[i].y += p * v4.y;
                o[i].z += p * v4.z; o[i].w += p * v4.w;
            }
        }
        __syncthreads();              // before next tile overwrites KVs/Ps
    }

    const float inv = 1.f / l;
    const int b = bh >> 4, h = bh & 15;
    float* dst = Out + ((size_t)(b * S_LEN + qtile * 64 + r)) * DMODEL
                     + h * HDIM + (half << 5);
#pragma unroll
    for (int i = 0; i < 8; i++) {
        float4 v4 = o[i];
        v4.x *= inv; v4.y *= inv; v4.z *= inv; v4.w *= inv;
        ((float4*)dst)[i] = v4;
    }
}

// ---------------------------------------------------------------------------
extern "C" void kernel_launch(void* const* d_in, const int* in_sizes, int n_in,
                              void* d_out, int out_size)
{
    const float* query = (const float*)d_in[0];
    const float* key   = (const float*)d_in[1];
    const float* value = (const float*)d_in[2];
    const float* Wq = (const float*)d_in[3];
    const float* bq = (const float*)d_in[4];
    const float* Wk = (const float*)d_in[5];
    const float* bk = (const float*)d_in[6];
    const float* Wv = (const float*)d_in[7];
    const float* bv = (const float*)d_in[8];
    const float* Wo = (const float*)d_in[9];
    const float* bo = (const float*)d_in[10];
    float* out = (float*)d_out;

    float *pQ, *pK, *pV, *pA;
    cudaGetSymbolAddress((void**)&pQ, g_Q);
    cudaGetSymbolAddress((void**)&pK, g_K);
    cudaGetSymbolAddress((void**)&pV, g_V);
    cudaGetSymbolAddress((void**)&pA, g_attn);

    dim3 ggrid(M_ROWS / 64, DMODEL / 64);
    gemm_bias_kernel<<<ggrid, 256>>>(query, Wq, bq, pQ, 1);
    gemm_bias_kernel<<<ggrid, 256>>>(key,   Wk, bk, pK, 1);
    gemm_bias_kernel<<<ggrid, 256>>>(value, Wv, bv, pV, 1);

    dim3 agrid(S_LEN / 64, BATCH * NHEAD);
    attn_kernel<<<agrid, 128>>>(pQ, pK, pV, pA);

    gemm_bias_kernel<<<ggrid, 256>>>(pA, Wo, bo, out, 0);
}

// round 3
// speedup vs baseline: 2.5727x; 2.5687x over previous
#include <cuda_runtime.h>

#define S_LEN   2048
#define DMODEL  1024
#define NHEAD   16
#define HDIM    64
#define BATCH   2
#define M_ROWS  (BATCH * S_LEN)   /* 4096 */

// Scratch (allocation-free rule: __device__ globals).
__device__ float g_Q[BATCH * NHEAD * S_LEN * HDIM];
__device__ float g_K[BATCH * NHEAD * S_LEN * HDIM];
__device__ float g_V[BATCH * NHEAD * S_LEN * HDIM];
__device__ float g_attn[BATCH * S_LEN * DMODEL];

// ---------------------------------------------------------------------------
// tf32 helpers
// ---------------------------------------------------------------------------
__device__ __forceinline__ unsigned f2tf(float x) {
    unsigned r;
    asm("cvt.rna.tf32.f32 %0, %1;" : "=r"(r) : "f"(x));
    return r;
}

// D += A * B  (m16n8k8, tf32 inputs, f32 accumulate)
__device__ __forceinline__ void mma8(float* d, const unsigned* a, const unsigned* b) {
    asm volatile(
        "mma.sync.aligned.m16n8k8.row.col.f32.tf32.tf32.f32 "
        "{%0,%1,%2,%3}, {%4,%5,%6,%7}, {%8,%9}, {%0,%1,%2,%3};\n"
        : "+f"(d[0]), "+f"(d[1]), "+f"(d[2]), "+f"(d[3])
        : "r"(a[0]), "r"(a[1]), "r"(a[2]), "r"(a[3]), "r"(b[0]), "r"(b[1]));
}

// ---------------------------------------------------------------------------
// 3xtf32 GEMM + bias:  C[m,n] = sum_k A[m,k] * W[n,k] + bias[n]
// CTA tile 128x128, BK=16, 256 threads (8 warps, 2Mx4N, warp tile 64x32).
// Full-precision via hi/lo tf32 split (drop lo*lo term).
// headsplit=1: write C to [B,H,S,64]; else flat [m,1024].
// ---------------------------------------------------------------------------
#define GST 20   /* smem row stride (floats): conflict-free for frag loads */

__global__ __launch_bounds__(256) void gemm_tf32_kernel(
    const float* __restrict__ A, const float* __restrict__ W,
    const float* __restrict__ bias, float* __restrict__ C, int headsplit)
{
    __shared__ unsigned Ah[128 * GST], Al[128 * GST];
    __shared__ unsigned Bh[128 * GST], Bl[128 * GST];

    const int tid  = threadIdx.x;
    const int lane = tid & 31;
    const int wid  = tid >> 5;
    const int wm   = wid >> 2;        // 0..1  -> 64 rows
    const int wn   = wid & 3;         // 0..3  -> 32 cols
    const int g    = lane >> 2;       // 0..7
    const int c    = lane & 3;        // 0..3
    const int bm   = blockIdx.x;
    const int bn   = blockIdx.y;

    const int lrow = tid >> 1;        // 0..127
    const int lk   = (tid & 1) << 3;  // 0 or 8

    const float* Ap = A + (size_t)(bm * 128 + lrow) * DMODEL + lk;
    const float* Wp = W + (size_t)(bn * 128 + lrow) * DMODEL + lk;

    float acc[4][4][4];
#pragma unroll
    for (int i = 0; i < 4; i++)
#pragma unroll
        for (int j = 0; j < 4; j++)
#pragma unroll
            for (int k = 0; k < 4; k++) acc[i][j][k] = 0.f;

    for (int k0 = 0; k0 < DMODEL; k0 += 16) {
        float4 av0 = *(const float4*)(Ap + k0);
        float4 av1 = *(const float4*)(Ap + k0 + 4);
        float4 wv0 = *(const float4*)(Wp + k0);
        float4 wv1 = *(const float4*)(Wp + k0 + 4);
        __syncthreads();   // previous iteration's reads done
        {
            const int base = lrow * GST + lk;
            float va[8] = {av0.x, av0.y, av0.z, av0.w, av1.x, av1.y, av1.z, av1.w};
            float vw[8] = {wv0.x, wv0.y, wv0.z, wv0.w, wv1.x, wv1.y, wv1.z, wv1.w};
            unsigned ha[8], la[8], hw[8], lw[8];
#pragma unroll
            for (int i = 0; i < 8; i++) {
                ha[i] = f2tf(va[i]);
                la[i] = f2tf(va[i] - __uint_as_float(ha[i]));
                hw[i] = f2tf(vw[i]);
                lw[i] = f2tf(vw[i] - __uint_as_float(hw[i]));
            }
            *(uint4*)&Ah[base]     = make_uint4(ha[0], ha[1], ha[2], ha[3]);
            *(uint4*)&Ah[base + 4] = make_uint4(ha[4], ha[5], ha[6], ha[7]);
            *(uint4*)&Al[base]     = make_uint4(la[0], la[1], la[2], la[3]);
            *(uint4*)&Al[base + 4] = make_uint4(la[4], la[5], la[6], la[7]);
            *(uint4*)&Bh[base]     = make_uint4(hw[0], hw[1], hw[2], hw[3]);
            *(uint4*)&Bh[base + 4] = make_uint4(hw[4], hw[5], hw[6], hw[7]);
            *(uint4*)&Bl[base]     = make_uint4(lw[0], lw[1], lw[2], lw[3]);
            *(uint4*)&Bl[base + 4] = make_uint4(lw[4], lw[5], lw[6], lw[7]);
        }
        __syncthreads();

#pragma unroll
        for (int ks = 0; ks < 16; ks += 8) {
            unsigned ah[4][4], al[4][4], bh[4][2], bl[4][2];
#pragma unroll
            for (int ma = 0; ma < 4; ma++) {
                const int r  = wm * 64 + ma * 16 + g;
                const int b0 = r * GST + ks + c;
                const int b1 = (r + 8) * GST + ks + c;
                ah[ma][0] = Ah[b0]; ah[ma][1] = Ah[b1];
                ah[ma][2] = Ah[b0 + 4]; ah[ma][3] = Ah[b1 + 4];
                al[ma][0] = Al[b0]; al[ma][1] = Al[b1];
                al[ma][2] = Al[b0 + 4]; al[ma][3] = Al[b1 + 4];
            }
#pragma unroll
            for (int na = 0; na < 4; na++) {
                const int n  = wn * 32 + na * 8 + g;
                const int nb = n * GST + ks + c;
                bh[na][0] = Bh[nb]; bh[na][1] = Bh[nb + 4];
                bl[na][0] = Bl[nb]; bl[na][1] = Bl[nb + 4];
            }
#pragma unroll
            for (int ma = 0; ma < 4; ma++)
#pragma unroll
                for (int na = 0; na < 4; na++) {
                    mma8(acc[ma][na], ah[ma], bl[na]);
                    mma8(acc[ma][na], al[ma], bh[na]);
                    mma8(acc[ma][na], ah[ma], bh[na]);
                }
        }
    }

    // epilogue
#pragma unroll
    for (int ma = 0; ma < 4; ma++) {
        const int m0 = bm * 128 + wm * 64 + ma * 16 + g;
#pragma unroll
        for (int na = 0; na < 4; na++) {
            const int n  = bn * 128 + wn * 32 + na * 8 + (c << 1);
            const float b0 = bias[n], b1 = bias[n + 1];
            float2 v0 = make_float2(acc[ma][na][0] + b0, acc[ma][na][1] + b1);
            float2 v1 = make_float2(acc[ma][na][2] + b0, acc[ma][na][3] + b1);
            if (headsplit) {
                const int h = n >> 6, d = n & 63;
                const int b_0 = m0 >> 11, s_0 = m0 & (S_LEN - 1);
                const int b_1 = (m0 + 8) >> 11, s_1 = (m0 + 8) & (S_LEN - 1);
                *(float2*)&C[((size_t)((b_0 * NHEAD + h) * S_LEN + s_0)) * HDIM + d] = v0;
                *(float2*)&C[((size_t)((b_1 * NHEAD + h) * S_LEN + s_1)) * HDIM + d] = v1;
            } else {
                *(float2*)&C[(size_t)m0 * DMODEL + n]       = v0;
                *(float2*)&C[(size_t)(m0 + 8) * DMODEL + n] = v1;
            }
        }
    }
}

// ---------------------------------------------------------------------------
// Flash attention, tf32 MMA.
// grid = (32 qtiles of 64 rows, B*H=32). 128 threads = 4 warps x 16 rows.
// Q pre-scaled by 1/8, held as tf32 A-fragments in registers.
// K smem stride 68 (B-frag conflict-free), V stride 72 (B-frag conflict-free),
// P stride 68 (A-frag conflict-free).
// ---------------------------------------------------------------------------
#define KS_ST 68
#define VS_ST 72
#define ATTN_SMEM ((64 * KS_ST + 64 * VS_ST + 64 * KS_ST) * 4)

__global__ __launch_bounds__(128) void attn_tf32_kernel(
    const float* __restrict__ Q, const float* __restrict__ K,
    const float* __restrict__ V, float* __restrict__ Out)
{
    extern __shared__ unsigned smem[];
    unsigned* Ks = smem;                       // 64 x 68
    unsigned* Vs = smem + 64 * KS_ST;          // 64 x 72
    unsigned* Ps = smem + 64 * KS_ST + 64 * VS_ST;  // 64 x 68

    const int tid  = threadIdx.x;
    const int lane = tid & 31;
    const int w    = tid >> 5;     // warp id: rows w*16 .. w*16+15
    const int g    = lane >> 2;
    const int c    = lane & 3;
    const int qtile = blockIdx.x;
    const int bh    = blockIdx.y;

    // Q fragments (scaled by 1/sqrt(64) = exact power of 2)
    const float* Qb = Q + ((size_t)bh * S_LEN + qtile * 64 + w * 16) * HDIM;
    unsigned qa[8][4];
#pragma unroll
    for (int ks = 0; ks < 8; ks++) {
        qa[ks][0] = f2tf(0.125f * Qb[(size_t)g * HDIM + ks * 8 + c]);
        qa[ks][1] = f2tf(0.125f * Qb[(size_t)(g + 8) * HDIM + ks * 8 + c]);
        qa[ks][2] = f2tf(0.125f * Qb[(size_t)g * HDIM + ks * 8 + c + 4]);
        qa[ks][3] = f2tf(0.125f * Qb[(size_t)(g + 8) * HDIM + ks * 8 + c + 4]);
    }

    float oacc[8][4];
#pragma unroll
    for (int i = 0; i < 8; i++)
#pragma unroll
        for (int j = 0; j < 4; j++) oacc[i][j] = 0.f;
    float m0 = -1e30f, m1 = -1e30f, l0 = 0.f, l1 = 0.f;

    const float* Kb = K + (size_t)bh * S_LEN * HDIM;
    const float* Vb = V + (size_t)bh * S_LEN * HDIM;

    for (int kt = 0; kt < S_LEN / 64; kt++) {
        // ---- load K,V tiles (convert to tf32) ----
        const float4* ksrc = (const float4*)(Kb + (size_t)kt * 64 * HDIM);
        const float4* vsrc = (const float4*)(Vb + (size_t)kt * 64 * HDIM);
#pragma unroll
        for (int i = 0; i < 8; i++) {
            const int f   = tid + i * 128;       // float4 index 0..1023
            const int row = f >> 4;
            const int col = (f & 15) << 2;
            float4 kv = ksrc[f];
            *(uint4*)&Ks[row * KS_ST + col] =
                make_uint4(f2tf(kv.x), f2tf(kv.y), f2tf(kv.z), f2tf(kv.w));
            float4 vv = vsrc[f];
            *(uint4*)&Vs[row * VS_ST + col] =
                make_uint4(f2tf(vv.x), f2tf(vv.y), f2tf(vv.z), f2tf(vv.w));
        }
        __syncthreads();

        // ---- S = (Q/8) @ K^T  (rows w*16..+15, cols 0..63) ----
        float sacc[8][4];
#pragma unroll
        for (int i = 0; i < 8; i++)
#pragma unroll
            for (int j = 0; j < 4; j++) sacc[i][j] = 0.f;
#pragma unroll
        for (int ks = 0; ks < 8; ks++) {
#pragma unroll
            for (int na = 0; na < 8; na++) {
                unsigned b[2];
                const int nb = (na * 8 + g) * KS_ST + ks * 8 + c;
                b[0] = Ks[nb];
                b[1] = Ks[nb + 4];
                mma8(sacc[na], qa[ks], b);
            }
        }

        // ---- online softmax ----
        float tm0 = -1e30f, tm1 = -1e30f;
#pragma unroll
        for (int na = 0; na < 8; na++) {
            tm0 = fmaxf(tm0, fmaxf(sacc[na][0], sacc[na][1]));
            tm1 = fmaxf(tm1, fmaxf(sacc[na][2], sacc[na][3]));
        }
        tm0 = fmaxf(tm0, __shfl_xor_sync(0xffffffffu, tm0, 1));
        tm0 = fmaxf(tm0, __shfl_xor_sync(0xffffffffu, tm0, 2));
        tm1 = fmaxf(tm1, __shfl_xor_sync(0xffffffffu, tm1, 1));
        tm1 = fmaxf(tm1, __shfl_xor_sync(0xffffffffu, tm1, 2));
        const float mn0 = fmaxf(m0, tm0);
        const float mn1 = fmaxf(m1, tm1);
        const float alpha0 = __expf(m0 - mn0);
        const float alpha1 = __expf(m1 - mn1);
        m0 = mn0; m1 = mn1;

        float rs0 = 0.f, rs1 = 0.f;
        const int pr0 = (w * 16 + g) * KS_ST;
        const int pr1 = (w * 16 + g + 8) * KS_ST;
#pragma unroll
        for (int na = 0; na < 8; na++) {
            const float p0 = __expf(sacc[na][0] - mn0);
            const float p1 = __expf(sacc[na][1] - mn0);
            const float p2 = __expf(sacc[na][2] - mn1);
            const float p3 = __expf(sacc[na][3] - mn1);
            rs0 += p0 + p1;
            rs1 += p2 + p3;
            const int col = na * 8 + (c << 1);
            *(uint2*)&Ps[pr0 + col] = make_uint2(f2tf(p0), f2tf(p1));
            *(uint2*)&Ps[pr1 + col] = make_uint2(f2tf(p2), f2tf(p3));
        }
        rs0 += __shfl_xor_sync(0xffffffffu, rs0, 1);
        rs0 += __shfl_xor_sync(0xffffffffu, rs0, 2);
        rs1 += __shfl_xor_sync(0xffffffffu, rs1, 1);
        rs1 += __shfl_xor_sync(0xffffffffu, rs1, 2);
        l0 = l0 * alpha0 + rs0;
        l1 = l1 * alpha1 + rs1;
#pragma unroll
        for (int na = 0; na < 8; na++) {
            oacc[na][0] *= alpha0; oacc[na][1] *= alpha0;
            oacc[na][2] *= alpha1; oacc[na][3] *= alpha1;
        }
        __syncwarp();   // Ps written by this warp, read by this warp below

        // ---- O += P @ V ----
#pragma unroll
        for (int ks = 0; ks < 8; ks++) {
            unsigned pa[4];
            const int pb = (w * 16 + g) * KS_ST + ks * 8 + c;
            pa[0] = Ps[pb];
            pa[1] = Ps[pb + 8 * KS_ST];
            pa[2] = Ps[pb + 4];
            pa[3] = Ps[pb + 8 * KS_ST + 4];
#pragma unroll
            for (int na = 0; na < 8; na++) {
                unsigned b[2];
                const int vb = (ks * 8 + c) * VS_ST + na * 8 + g;
                b[0] = Vs[vb];
                b[1] = Vs[vb + 4 * VS_ST];
                mma8(oacc[na], pa, b);
            }
        }
        __syncthreads();   // all reads done before next tile's stores
    }

    // ---- epilogue ----
    const float inv0 = 1.f / l0;
    const float inv1 = 1.f / l1;
    const int b = bh >> 4, h = bh & 15;
    const int s0 = qtile * 64 + w * 16 + g;
    float* o0 = Out + ((size_t)(b * S_LEN + s0)) * DMODEL + h * HDIM;
    float* o1 = o0 + (size_t)8 * DMODEL;
#pragma unroll
    for (int na = 0; na < 8; na++) {
        const int col = na * 8 + (c << 1);
        *(float2*)(o0 + col) = make_float2(oacc[na][0] * inv0, oacc[na][1] * inv0);
        *(float2*)(o1 + col) = make_float2(oacc[na][2] * inv1, oacc[na][3] * inv1);
    }
}

// ---------------------------------------------------------------------------
extern "C" void kernel_launch(void* const* d_in, const int* in_sizes, int n_in,
                              void* d_out, int out_size)
{
    const float* query = (const float*)d_in[0];
    const float* key   = (const float*)d_in[1];
    const float* value = (const float*)d_in[2];
    const float* Wq = (const float*)d_in[3];
    const float* bq = (const float*)d_in[4];
    const float* Wk = (const float*)d_in[5];
    const float* bk = (const float*)d_in[6];
    const float* Wv = (const float*)d_in[7];
    const float* bv = (const float*)d_in[8];
    const float* Wo = (const float*)d_in[9];
    const float* bo = (const float*)d_in[10];
    float* out = (float*)d_out;

    float *pQ, *pK, *pV, *pA;
    cudaGetSymbolAddress((void**)&pQ, g_Q);
    cudaGetSymbolAddress((void**)&pK, g_K);
    cudaGetSymbolAddress((void**)&pV, g_V);
    cudaGetSymbolAddress((void**)&pA, g_attn);

    static int smem_set = 0;
    if (!smem_set) {
        cudaFuncSetAttribute(attn_tf32_kernel,
                             cudaFuncAttributeMaxDynamicSharedMemorySize,
                             ATTN_SMEM);
        smem_set = 1;
    }

    dim3 ggrid(M_ROWS / 128, DMODEL / 128);
    gemm_tf32_kernel<<<ggrid, 256>>>(query, Wq, bq, pQ, 1);
    gemm_tf32_kernel<<<ggrid, 256>>>(key,   Wk, bk, pK, 1);
    gemm_tf32_kernel<<<ggrid, 256>>>(value, Wv, bv, pV, 1);

    dim3 agrid(S_LEN / 64, BATCH * NHEAD);
    attn_tf32_kernel<<<agrid, 128, ATTN_SMEM>>>(pQ, pK, pV, pA);

    gemm_tf32_kernel<<<ggrid, 256>>>(pA, Wo, bo, out, 0);
}

// round 4
// speedup vs baseline: 3.5468x; 1.3786x over previous
#include <cuda_runtime.h>
#include <cuda_bf16.h>

#define S_LEN   2048
#define DMODEL  1024
#define NHEAD   16
#define HDIM    64
#define BATCH   2
#define M_ROWS  (BATCH * S_LEN)   /* 4096 */

// Scratch (allocation-free rule: __device__ globals).
__device__ float g_Q[BATCH * NHEAD * S_LEN * HDIM];
__device__ float g_K[BATCH * NHEAD * S_LEN * HDIM];
__device__ float g_V[BATCH * NHEAD * S_LEN * HDIM];
__device__ float g_attn[BATCH * S_LEN * DMODEL];

// ---------------------------------------------------------------------------
// helpers
// ---------------------------------------------------------------------------
__device__ __forceinline__ unsigned f2tf(float x) {
    unsigned r;
    asm("cvt.rna.tf32.f32 %0, %1;" : "=r"(r) : "f"(x));
    return r;
}

// D += A * B  (m16n8k8, tf32 inputs, f32 accumulate)
__device__ __forceinline__ void mma8(float* d, const unsigned* a, const unsigned* b) {
    asm volatile(
        "mma.sync.aligned.m16n8k8.row.col.f32.tf32.tf32.f32 "
        "{%0,%1,%2,%3}, {%4,%5,%6,%7}, {%8,%9}, {%0,%1,%2,%3};\n"
        : "+f"(d[0]), "+f"(d[1]), "+f"(d[2]), "+f"(d[3])
        : "r"(a[0]), "r"(a[1]), "r"(a[2]), "r"(a[3]), "r"(b[0]), "r"(b[1]));
}

// D += A * B  (m16n8k16, bf16 inputs, f32 accumulate)
__device__ __forceinline__ void mma16(float* d, const unsigned* a, const unsigned* b) {
    asm volatile(
        "mma.sync.aligned.m16n8k16.row.col.f32.bf16.bf16.f32 "
        "{%0,%1,%2,%3}, {%4,%5,%6,%7}, {%8,%9}, {%0,%1,%2,%3};\n"
        : "+f"(d[0]), "+f"(d[1]), "+f"(d[2]), "+f"(d[3])
        : "r"(a[0]), "r"(a[1]), "r"(a[2]), "r"(a[3]), "r"(b[0]), "r"(b[1]));
}

__device__ __forceinline__ unsigned bfpack(float lo_k, float hi_k) {
    __nv_bfloat162 t = __floats2bfloat162_rn(lo_k, hi_k);  // .x = even k (low)
    return *(unsigned*)&t;
}

// ---------------------------------------------------------------------------
// 3xbf16-split GEMM + bias:  C[m,n] = sum_k A[m,k] * W[n,k] + bias[n]
// CTA tile 128x128, BK=16, 256 threads (8 warps, 2Mx4N, warp tile 64x32).
// x = hi + lo (both bf16); compute hi*hi + hi*lo + lo*hi (drop lo*lo ~2^-18).
// k-pairs packed in 32-bit words -> one LDS feeds a k16 MMA operand reg.
// Smem word stride 12: conflict-free for (g,c) fragment loads.
// headsplit=1: write C to [B,H,S,64]; else flat [m,1024].
// ---------------------------------------------------------------------------
#define GW 12   /* smem row stride in 32-bit words (8 words data + 4 pad) */

__global__ __launch_bounds__(256) void gemm_bf16_kernel(
    const float* __restrict__ A, const float* __restrict__ W,
    const float* __restrict__ bias, float* __restrict__ C, int headsplit)
{
    __shared__ unsigned Ah[128 * GW], Al[128 * GW];
    __shared__ unsigned Bh[128 * GW], Bl[128 * GW];

    const int tid  = threadIdx.x;
    const int lane = tid & 31;
    const int wid  = tid >> 5;
    const int wm   = wid >> 2;        // 0..1  -> 64 rows
    const int wn   = wid & 3;         // 0..3  -> 32 cols
    const int g    = lane >> 2;       // 0..7
    const int c    = lane & 3;        // 0..3
    const int bm   = blockIdx.x;
    const int bn   = blockIdx.y;

    const int lrow = tid >> 1;        // 0..127
    const int lk   = (tid & 1) << 3;  // float-k offset: 0 or 8
    const int wbase = lrow * GW + (lk >> 1);  // word offset: 0 or 4

    const float* Ap = A + (size_t)(bm * 128 + lrow) * DMODEL + lk;
    const float* Wp = W + (size_t)(bn * 128 + lrow) * DMODEL + lk;

    float acc[4][4][4];
#pragma unroll
    for (int i = 0; i < 4; i++)
#pragma unroll
        for (int j = 0; j < 4; j++)
#pragma unroll
            for (int k = 0; k < 4; k++) acc[i][j][k] = 0.f;

    // prologue gmem load
    float4 rA0 = *(const float4*)(Ap);
    float4 rA1 = *(const float4*)(Ap + 4);
    float4 rW0 = *(const float4*)(Wp);
    float4 rW1 = *(const float4*)(Wp + 4);

    for (int k0 = 0; k0 < DMODEL; k0 += 16) {
        // ---- convert current regs to hi/lo bf16 pairs ----
        float va[8] = {rA0.x, rA0.y, rA0.z, rA0.w, rA1.x, rA1.y, rA1.z, rA1.w};
        float vw[8] = {rW0.x, rW0.y, rW0.z, rW0.w, rW1.x, rW1.y, rW1.z, rW1.w};
        float hafl[8], hwfl[8];
        unsigned ha[4], la[4], hw[4], lw[4];
#pragma unroll
        for (int i = 0; i < 8; i++) {
            hafl[i] = __bfloat162float(__float2bfloat16_rn(va[i]));
            hwfl[i] = __bfloat162float(__float2bfloat16_rn(vw[i]));
        }
#pragma unroll
        for (int i = 0; i < 4; i++) {
            ha[i] = bfpack(hafl[2*i], hafl[2*i+1]);
            la[i] = bfpack(va[2*i] - hafl[2*i], va[2*i+1] - hafl[2*i+1]);
            hw[i] = bfpack(hwfl[2*i], hwfl[2*i+1]);
            lw[i] = bfpack(vw[2*i] - hwfl[2*i], vw[2*i+1] - hwfl[2*i+1]);
        }

        __syncthreads();   // previous iteration's fragment reads done
        *(uint4*)&Ah[wbase] = make_uint4(ha[0], ha[1], ha[2], ha[3]);
        *(uint4*)&Al[wbase] = make_uint4(la[0], la[1], la[2], la[3]);
        *(uint4*)&Bh[wbase] = make_uint4(hw[0], hw[1], hw[2], hw[3]);
        *(uint4*)&Bl[wbase] = make_uint4(lw[0], lw[1], lw[2], lw[3]);
        __syncthreads();

        // ---- prefetch next tile's gmem data (overlaps MMA phase) ----
        if (k0 + 16 < DMODEL) {
            rA0 = *(const float4*)(Ap + k0 + 16);
            rA1 = *(const float4*)(Ap + k0 + 20);
            rW0 = *(const float4*)(Wp + k0 + 16);
            rW1 = *(const float4*)(Wp + k0 + 20);
        }

        // ---- fragments + MMAs (one k16 step covers the whole 16-k tile) ----
        unsigned ah[4][4], al[4][4], bh[4][2], bl[4][2];
#pragma unroll
        for (int ma = 0; ma < 4; ma++) {
            const int r  = wm * 64 + ma * 16 + g;
            const int b0 = r * GW + c;
            const int b1 = (r + 8) * GW + c;
            ah[ma][0] = Ah[b0]; ah[ma][1] = Ah[b1];
            ah[ma][2] = Ah[b0 + 4]; ah[ma][3] = Ah[b1 + 4];
            al[ma][0] = Al[b0]; al[ma][1] = Al[b1];
            al[ma][2] = Al[b0 + 4]; al[ma][3] = Al[b1 + 4];
        }
#pragma unroll
        for (int na = 0; na < 4; na++) {
            const int nb = (wn * 32 + na * 8 + g) * GW + c;
            bh[na][0] = Bh[nb]; bh[na][1] = Bh[nb + 4];
            bl[na][0] = Bl[nb]; bl[na][1] = Bl[nb + 4];
        }
#pragma unroll
        for (int ma = 0; ma < 4; ma++)
#pragma unroll
            for (int na = 0; na < 4; na++) {
                mma16(acc[ma][na], ah[ma], bl[na]);
                mma16(acc[ma][na], al[ma], bh[na]);
                mma16(acc[ma][na], ah[ma], bh[na]);
            }
    }

    // epilogue
#pragma unroll
    for (int ma = 0; ma < 4; ma++) {
        const int m0 = bm * 128 + wm * 64 + ma * 16 + g;
#pragma unroll
        for (int na = 0; na < 4; na++) {
            const int n  = bn * 128 + wn * 32 + na * 8 + (c << 1);
            const float b0 = bias[n], b1 = bias[n + 1];
            float2 v0 = make_float2(acc[ma][na][0] + b0, acc[ma][na][1] + b1);
            float2 v1 = make_float2(acc[ma][na][2] + b0, acc[ma][na][3] + b1);
            if (headsplit) {
                const int h = n >> 6, d = n & 63;
                const int b_0 = m0 >> 11, s_0 = m0 & (S_LEN - 1);
                const int b_1 = (m0 + 8) >> 11, s_1 = (m0 + 8) & (S_LEN - 1);
                *(float2*)&C[((size_t)((b_0 * NHEAD + h) * S_LEN + s_0)) * HDIM + d] = v0;
                *(float2*)&C[((size_t)((b_1 * NHEAD + h) * S_LEN + s_1)) * HDIM + d] = v1;
            } else {
                *(float2*)&C[(size_t)m0 * DMODEL + n]       = v0;
                *(float2*)&C[(size_t)(m0 + 8) * DMODEL + n] = v1;
            }
        }
    }
}

// ---------------------------------------------------------------------------
// Flash attention, tf32 MMA (unchanged from round 2 — known good).
// grid = (32 qtiles of 64 rows, B*H=32). 128 threads = 4 warps x 16 rows.
// ---------------------------------------------------------------------------
#define KS_ST 68
#define VS_ST 72
#define ATTN_SMEM ((64 * KS_ST + 64 * VS_ST + 64 * KS_ST) * 4)

__global__ __launch_bounds__(128) void attn_tf32_kernel(
    const float* __restrict__ Q, const float* __restrict__ K,
    const float* __restrict__ V, float* __restrict__ Out)
{
    extern __shared__ unsigned smem[];
    unsigned* Ks = smem;                       // 64 x 68
    unsigned* Vs = smem + 64 * KS_ST;          // 64 x 72
    unsigned* Ps = smem + 64 * KS_ST + 64 * VS_ST;  // 64 x 68

    const int tid  = threadIdx.x;
    const int lane = tid & 31;
    const int w    = tid >> 5;
    const int g    = lane >> 2;
    const int c    = lane & 3;
    const int qtile = blockIdx.x;
    const int bh    = blockIdx.y;

    const float* Qb = Q + ((size_t)bh * S_LEN + qtile * 64 + w * 16) * HDIM;
    unsigned qa[8][4];
#pragma unroll
    for (int ks = 0; ks < 8; ks++) {
        qa[ks][0] = f2tf(0.125f * Qb[(size_t)g * HDIM + ks * 8 + c]);
        qa[ks][1] = f2tf(0.125f * Qb[(size_t)(g + 8) * HDIM + ks * 8 + c]);
        qa[ks][2] = f2tf(0.125f * Qb[(size_t)g * HDIM + ks * 8 + c + 4]);
        qa[ks][3] = f2tf(0.125f * Qb[(size_t)(g + 8) * HDIM + ks * 8 + c + 4]);
    }

    float oacc[8][4];
#pragma unroll
    for (int i = 0; i < 8; i++)
#pragma unroll
        for (int j = 0; j < 4; j++) oacc[i][j] = 0.f;
    float m0 = -1e30f, m1 = -1e30f, l0 = 0.f, l1 = 0.f;

    const float* Kb = K + (size_t)bh * S_LEN * HDIM;
    const float* Vb = V + (size_t)bh * S_LEN * HDIM;

    for (int kt = 0; kt < S_LEN / 64; kt++) {
        const float4* ksrc = (const float4*)(Kb + (size_t)kt * 64 * HDIM);
        const float4* vsrc = (const float4*)(Vb + (size_t)kt * 64 * HDIM);
#pragma unroll
        for (int i = 0; i < 8; i++) {
            const int f   = tid + i * 128;
            const int row = f >> 4;
            const int col = (f & 15) << 2;
            float4 kv = ksrc[f];
            *(uint4*)&Ks[row * KS_ST + col] =
                make_uint4(f2tf(kv.x), f2tf(kv.y), f2tf(kv.z), f2tf(kv.w));
            float4 vv = vsrc[f];
            *(uint4*)&Vs[row * VS_ST + col] =
                make_uint4(f2tf(vv.x), f2tf(vv.y), f2tf(vv.z), f2tf(vv.w));
        }
        __syncthreads();

        float sacc[8][4];
#pragma unroll
        for (int i = 0; i < 8; i++)
#pragma unroll
            for (int j = 0; j < 4; j++) sacc[i][j] = 0.f;
#pragma unroll
        for (int ks = 0; ks < 8; ks++) {
#pragma unroll
            for (int na = 0; na < 8; na++) {
                unsigned b[2];
                const int nb = (na * 8 + g) * KS_ST + ks * 8 + c;
                b[0] = Ks[nb];
                b[1] = Ks[nb + 4];
                mma8(sacc[na], qa[ks], b);
            }
        }

        float tm0 = -1e30f, tm1 = -1e30f;
#pragma unroll
        for (int na = 0; na < 8; na++) {
            tm0 = fmaxf(tm0, fmaxf(sacc[na][0], sacc[na][1]));
            tm1 = fmaxf(tm1, fmaxf(sacc[na][2], sacc[na][3]));
        }
        tm0 = fmaxf(tm0, __shfl_xor_sync(0xffffffffu, tm0, 1));
        tm0 = fmaxf(tm0, __shfl_xor_sync(0xffffffffu, tm0, 2));
        tm1 = fmaxf(tm1, __shfl_xor_sync(0xffffffffu, tm1, 1));
        tm1 = fmaxf(tm1, __shfl_xor_sync(0xffffffffu, tm1, 2));
        const float mn0 = fmaxf(m0, tm0);
        const float mn1 = fmaxf(m1, tm1);
        const float alpha0 = __expf(m0 - mn0);
        const float alpha1 = __expf(m1 - mn1);
        m0 = mn0; m1 = mn1;

        float rs0 = 0.f, rs1 = 0.f;
        const int pr0 = (w * 16 + g) * KS_ST;
        const int pr1 = (w * 16 + g + 8) * KS_ST;
#pragma unroll
        for (int na = 0; na < 8; na++) {
            const float p0 = __expf(sacc[na][0] - mn0);
            const float p1 = __expf(sacc[na][1] - mn0);
            const float p2 = __expf(sacc[na][2] - mn1);
            const float p3 = __expf(sacc[na][3] - mn1);
            rs0 += p0 + p1;
            rs1 += p2 + p3;
            const int col = na * 8 + (c << 1);
            *(uint2*)&Ps[pr0 + col] = make_uint2(f2tf(p0), f2tf(p1));
            *(uint2*)&Ps[pr1 + col] = make_uint2(f2tf(p2), f2tf(p3));
        }
        rs0 += __shfl_xor_sync(0xffffffffu, rs0, 1);
        rs0 += __shfl_xor_sync(0xffffffffu, rs0, 2);
        rs1 += __shfl_xor_sync(0xffffffffu, rs1, 1);
        rs1 += __shfl_xor_sync(0xffffffffu, rs1, 2);
        l0 = l0 * alpha0 + rs0;
        l1 = l1 * alpha1 + rs1;
#pragma unroll
        for (int na = 0; na < 8; na++) {
            oacc[na][0] *= alpha0; oacc[na][1] *= alpha0;
            oacc[na][2] *= alpha1; oacc[na][3] *= alpha1;
        }
        __syncwarp();

#pragma unroll
        for (int ks = 0; ks < 8; ks++) {
            unsigned pa[4];
            const int pb = (w * 16 + g) * KS_ST + ks * 8 + c;
            pa[0] = Ps[pb];
            pa[1] = Ps[pb + 8 * KS_ST];
            pa[2] = Ps[pb + 4];
            pa[3] = Ps[pb + 8 * KS_ST + 4];
#pragma unroll
            for (int na = 0; na < 8; na++) {
                unsigned b[2];
                const int vb = (ks * 8 + c) * VS_ST + na * 8 + g;
                b[0] = Vs[vb];
                b[1] = Vs[vb + 4 * VS_ST];
                mma8(oacc[na], pa, b);
            }
        }
        __syncthreads();
    }

    const float inv0 = 1.f / l0;
    const float inv1 = 1.f / l1;
    const int b = bh >> 4, h = bh & 15;
    const int s0 = qtile * 64 + w * 16 + g;
    float* o0 = Out + ((size_t)(b * S_LEN + s0)) * DMODEL + h * HDIM;
    float* o1 = o0 + (size_t)8 * DMODEL;
#pragma unroll
    for (int na = 0; na < 8; na++) {
        const int col = na * 8 + (c << 1);
        *(float2*)(o0 + col) = make_float2(oacc[na][0] * inv0, oacc[na][1] * inv0);
        *(float2*)(o1 + col) = make_float2(oacc[na][2] * inv1, oacc[na][3] * inv1);
    }
}

// ---------------------------------------------------------------------------
extern "C" void kernel_launch(void* const* d_in, const int* in_sizes, int n_in,
                              void* d_out, int out_size)
{
    const float* query = (const float*)d_in[0];
    const float* key   = (const float*)d_in[1];
    const float* value = (const float*)d_in[2];
    const float* Wq = (const float*)d_in[3];
    const float* bq = (const float*)d_in[4];
    const float* Wk = (const float*)d_in[5];
    const float* bk = (const float*)d_in[6];
    const float* Wv = (const float*)d_in[7];
    const float* bv = (const float*)d_in[8];
    const float* Wo = (const float*)d_in[9];
    const float* bo = (const float*)d_in[10];
    float* out = (float*)d_out;

    float *pQ, *pK, *pV, *pA;
    cudaGetSymbolAddress((void**)&pQ, g_Q);
    cudaGetSymbolAddress((void**)&pK, g_K);
    cudaGetSymbolAddress((void**)&pV, g_V);
    cudaGetSymbolAddress((void**)&pA, g_attn);

    static int smem_set = 0;
    if (!smem_set) {
        cudaFuncSetAttribute(attn_tf32_kernel,
                             cudaFuncAttributeMaxDynamicSharedMemorySize,
                             ATTN_SMEM);
        smem_set = 1;
    }

    dim3 ggrid(M_ROWS / 128, DMODEL / 128);
    gemm_bf16_kernel<<<ggrid, 256>>>(query, Wq, bq, pQ, 1);
    gemm_bf16_kernel<<<ggrid, 256>>>(key,   Wk, bk, pK, 1);
    gemm_bf16_kernel<<<ggrid, 256>>>(value, Wv, bv, pV, 1);

    dim3 agrid(S_LEN / 64, BATCH * NHEAD);
    attn_tf32_kernel<<<agrid, 128, ATTN_SMEM>>>(pQ, pK, pV, pA);

    gemm_bf16_kernel<<<ggrid, 256>>>(pA, Wo, bo, out, 0);
}